// round 11
// baseline (speedup 1.0000x reference)
#include <cuda_runtime.h>
#include <cuda_bf16.h>
#include <cuda_fp16.h>
#include <cstdint>

// Problem constants: B=8, T=12, N=512, D_MODEL=128, K_HEADS=8, D_HEAD=16.
#define DMODEL   128
#define KHEADS   8
#define DHEAD    16
#define NSEQ     512
#define MMAX     49152

// ---------------- generic-ISA tensor helpers (compute_103-safe) ------------
__device__ __forceinline__ uint32_t smem_to_u32(const void* p) {
    uint32_t a;
    asm("{ .reg .u64 t; cvta.to.shared.u64 t, %1; cvt.u32.u64 %0, t; }"
        : "=r"(a) : "l"(p));
    return a;
}
__device__ __forceinline__ void ldsm_x4(uint32_t* r, uint32_t addr) {
    asm volatile("ldmatrix.sync.aligned.m8n8.x4.shared.b16 {%0,%1,%2,%3}, [%4];"
                 : "=r"(r[0]), "=r"(r[1]), "=r"(r[2]), "=r"(r[3]) : "r"(addr));
}
__device__ __forceinline__ void ldsm_x4t(uint32_t* r, uint32_t addr) {
    asm volatile("ldmatrix.sync.aligned.m8n8.x4.trans.shared.b16 {%0,%1,%2,%3}, [%4];"
                 : "=r"(r[0]), "=r"(r[1]), "=r"(r[2]), "=r"(r[3]) : "r"(addr));
}
__device__ __forceinline__ void mma_bf16(float* d, const uint32_t* a,
                                         uint32_t b0, uint32_t b1) {
    asm volatile("mma.sync.aligned.m16n8k16.row.col.f32.bf16.bf16.f32 "
                 "{%0,%1,%2,%3}, {%4,%5,%6,%7}, {%8,%9}, {%0,%1,%2,%3};"
                 : "+f"(d[0]), "+f"(d[1]), "+f"(d[2]), "+f"(d[3])
                 : "r"(a[0]), "r"(a[1]), "r"(a[2]), "r"(a[3]), "r"(b0), "r"(b1));
}
__device__ __forceinline__ void mma_f16(float* d, const uint32_t* a,
                                        uint32_t b0, uint32_t b1) {
    asm volatile("mma.sync.aligned.m16n8k16.row.col.f32.f16.f16.f32 "
                 "{%0,%1,%2,%3}, {%4,%5,%6,%7}, {%8,%9}, {%0,%1,%2,%3};"
                 : "+f"(d[0]), "+f"(d[1]), "+f"(d[2]), "+f"(d[3])
                 : "r"(a[0]), "r"(a[1]), "r"(a[2]), "r"(a[3]), "r"(b0), "r"(b1));
}
#define CP_ASYNC16(dst_u32, src_ptr) \
    asm volatile("cp.async.ca.shared.global [%0], [%1], 16;" \
                 :: "r"(dst_u32), "l"(src_ptr))
#define CP_COMMIT() asm volatile("cp.async.commit_group;" ::: "memory")
#define CP_WAIT(n)  asm volatile("cp.async.wait_group %0;" :: "n"(n) : "memory")

// cheap split: packed cvt + shift-unpack (bf16->f32 is a 16-bit shift)
__device__ __forceinline__ void split2(float x, float y, uint32_t& hi, uint32_t& lo) {
    uint32_t h;
    asm("cvt.rn.bf16x2.f32 %0, %1, %2;" : "=r"(h) : "f"(y), "f"(x));
    const float hx = __uint_as_float(h << 16);
    const float hy = __uint_as_float(h & 0xffff0000u);
    uint32_t l;
    asm("cvt.rn.bf16x2.f32 %0, %1, %2;" : "=r"(l) : "f"(y - hy), "f"(x - hx));
    hi = h; lo = l;
}
__device__ __forceinline__ uint32_t packh2(float x, float y) {
    const half2 h = __floats2half2_rn(x, y);
    return *(const uint32_t*)&h;
}
__device__ __forceinline__ void splitH2(float x, float y, uint32_t& hi, uint32_t& lo) {
    const half2 h = __floats2half2_rn(x, y);
    const float2 hf = __half22float2(h);
    const half2 l = __floats2half2_rn(x - hf.x, y - hf.y);
    hi = *(const uint32_t*)&h;
    lo = *(const uint32_t*)&l;
}

// ---------------- scratch --------------------------------------------------
__device__ float g_q[(size_t)MMAX * DMODEL];
__device__ float g_k[(size_t)MMAX * DMODEL];
__device__ float g_v[(size_t)MMAX * DMODEL];
__device__ __nv_bfloat16 g_ahi[(size_t)MMAX * 384];
__device__ __nv_bfloat16 g_alo[(size_t)MMAX * 384];
__device__ __nv_bfloat16 g_ohi[(size_t)MMAX * DMODEL];
__device__ __nv_bfloat16 g_olo[(size_t)MMAX * DMODEL];
#define W_TOTAL (3 * 49152 + 16384)
__device__ __nv_bfloat16 g_whi[W_TOTAL];
__device__ __nv_bfloat16 g_wlo[W_TOTAL];
#define WOFF_O 147456

// ===========================================================================
// Pre-split kernels
// ===========================================================================
__global__ void presplit_x_kernel(const float* __restrict__ X,
                                  const float* __restrict__ STE, int M,
                                  __nv_bfloat16* __restrict__ ahi,
                                  __nv_bfloat16* __restrict__ alo)
{
    const int total = M * 96;
    for (int i = blockIdx.x * blockDim.x + threadIdx.x; i < total;
         i += gridDim.x * blockDim.x) {
        const int m = i / 96, c = (i % 96) * 4;
        const float4 x = (c < 128)
            ? *(const float4*)&X[(size_t)m * 128 + c]
            : *(const float4*)&STE[(size_t)m * 256 + (c - 128)];
        uint32_t h0, l0, h1, l1;
        split2(x.x, x.y, h0, l0);
        split2(x.z, x.w, h1, l1);
        *(uint2*)&ahi[(size_t)m * 384 + c] = make_uint2(h0, h1);
        *(uint2*)&alo[(size_t)m * 384 + c] = make_uint2(l0, l1);
    }
}

__global__ void presplit_w_kernel(const float* __restrict__ Wq,
                                  const float* __restrict__ Wk,
                                  const float* __restrict__ Wv,
                                  const float* __restrict__ Wo,
                                  __nv_bfloat16* __restrict__ whi,
                                  __nv_bfloat16* __restrict__ wlo)
{
    const int i = blockIdx.x * blockDim.x + threadIdx.x;
    if (i >= W_TOTAL / 4) return;
    const float* src; int off;
    if      (i < 12288) { src = Wq; off = 0; }
    else if (i < 24576) { src = Wk; off = 12288; }
    else if (i < 36864) { src = Wv; off = 24576; }
    else                { src = Wo; off = 36864; }
    const int j = (i - off) * 4;
    const float4 x = *(const float4*)&src[j];
    uint32_t h0, l0, h1, l1;
    split2(x.x, x.y, h0, l0);
    split2(x.z, x.w, h1, l1);
    *(uint2*)&whi[off * 4 + j] = make_uint2(h0, h1);
    *(uint2*)&wlo[off * 4 + j] = make_uint2(l0, l1);
}

// ===========================================================================
// Pipelined mma.sync GEMM core (shared by QKV-fused and out-proj kernels).
// cp.async 2-stage double buffering, K-chunks of 32, occupancy 2.
// 8 warps: 4m x 2n; warp tile 32x64; acc[2][8][4] = 64 regs.
// ===========================================================================
#define GK      32
#define GA_LD   40                       // 32 + 8 pad elems
#define GB_LD   136                      // 128 + 8 pad elems
#define GA_BUF  (128 * GA_LD * 2)        // 10240 B per (buf,hl)
#define GB_BUF  (GK * GB_LD * 2)         // 8704 B per (buf,hl)
#define GSM_A   0
#define GSM_B   (4 * GA_BUF)             // 40960
#define GEMM_SMEM (GSM_B + 4 * GB_BUF)   // 75776 bytes

__device__ __forceinline__ void gemm_core(
    const __nv_bfloat16* __restrict__ Ahi,
    const __nv_bfloat16* __restrict__ Alo,
    int lda, int K, int rowBase,
    const __nv_bfloat16* __restrict__ Whi,
    const __nv_bfloat16* __restrict__ Wlo,
    const float* __restrict__ bias, float* __restrict__ C,
    char* smc, uint32_t sb)
{
    const int tid  = threadIdx.x;
    const int warp = tid >> 5;
    const int lane = tid & 31;
    const int wm   = warp & 3;
    const int wn   = warp >> 2;

    float acc[2][8][4];
#pragma unroll
    for (int mt = 0; mt < 2; mt++)
#pragma unroll
        for (int nt = 0; nt < 8; nt++)
#pragma unroll
            for (int e = 0; e < 4; e++) acc[mt][nt][e] = 0.0f;

    const int nChunks = K / GK;

    auto load_chunk = [&](int c, int buf) {
        const int k0 = c * GK;
        {
            const int r = tid >> 1;
#pragma unroll
            for (int hl = 0; hl < 2; hl++) {
                const __nv_bfloat16* gsrc =
                    (hl ? Alo : Ahi) + (size_t)(rowBase + r) * lda + k0;
                const uint32_t dbase =
                    sb + GSM_A + (buf * 2 + hl) * GA_BUF + r * (GA_LD * 2);
#pragma unroll
                for (int s2 = 0; s2 < 2; s2++) {
                    const int s = (tid & 1) * 2 + s2;
                    CP_ASYNC16(dbase + s * 16, gsrc + s * 8);
                }
            }
        }
        {
            const int kk = tid >> 3;
#pragma unroll
            for (int hl = 0; hl < 2; hl++) {
                const __nv_bfloat16* gsrc =
                    (hl ? Wlo : Whi) + (size_t)(k0 + kk) * 128;
                const uint32_t dbase =
                    sb + GSM_B + (buf * 2 + hl) * GB_BUF + kk * (GB_LD * 2);
#pragma unroll
                for (int s2 = 0; s2 < 2; s2++) {
                    const int s = (tid & 7) * 2 + s2;
                    CP_ASYNC16(dbase + s * 16, gsrc + s * 8);
                }
            }
        }
        CP_COMMIT();
    };

    load_chunk(0, 0);

    for (int c = 0; c < nChunks; c++) {
        if (c + 1 < nChunks) { load_chunk(c + 1, (c + 1) & 1); CP_WAIT(1); }
        else                 { CP_WAIT(0); }
        __syncthreads();

        const int buf = c & 1;
        const uint32_t abase_h = sb + GSM_A + (buf * 2 + 0) * GA_BUF;
        const uint32_t abase_l = sb + GSM_A + (buf * 2 + 1) * GA_BUF;
        const uint32_t bbase_h = sb + GSM_B + (buf * 2 + 0) * GB_BUF;
        const uint32_t bbase_l = sb + GSM_B + (buf * 2 + 1) * GB_BUF;

#pragma unroll
        for (int ks = 0; ks < 2; ks++) {
            uint32_t ah[2][4], al[2][4];
            const int arow = lane & 15;
            const int acol = ks * 16 + (lane >> 4) * 8;
#pragma unroll
            for (int mt = 0; mt < 2; mt++) {
                const uint32_t aoff =
                    ((wm * 32 + mt * 16 + arow) * GA_LD + acol) * 2;
                ldsm_x4(ah[mt], abase_h + aoff);
                ldsm_x4(al[mt], abase_l + aoff);
            }
            const int brow = ks * 16 + (lane & 15);
#pragma unroll
            for (int np = 0; np < 4; np++) {
                const uint32_t boff =
                    (brow * GB_LD + wn * 64 + np * 16 + (lane >> 4) * 8) * 2;
                uint32_t bh[4], bl[4];
                ldsm_x4t(bh, bbase_h + boff);
                ldsm_x4t(bl, bbase_l + boff);
#pragma unroll
                for (int sub = 0; sub < 2; sub++) {
                    const int nt = np * 2 + sub;
#pragma unroll
                    for (int mt = 0; mt < 2; mt++) {
                        mma_bf16(acc[mt][nt], ah[mt], bh[2 * sub], bh[2 * sub + 1]);
                        mma_bf16(acc[mt][nt], ah[mt], bl[2 * sub], bl[2 * sub + 1]);
                        mma_bf16(acc[mt][nt], al[mt], bh[2 * sub], bh[2 * sub + 1]);
                    }
                }
            }
        }
        __syncthreads();
    }

#pragma unroll
    for (int mt = 0; mt < 2; mt++) {
        const int r0 = rowBase + wm * 32 + mt * 16 + (lane >> 2);
#pragma unroll
        for (int nt = 0; nt < 8; nt++) {
            const int cc = wn * 64 + nt * 8 + (lane & 3) * 2;
            const float b0 = bias[cc], b1 = bias[cc + 1];
            float2 lo, hi;
            lo.x = fmaxf(acc[mt][nt][0] + b0, 0.0f);
            lo.y = fmaxf(acc[mt][nt][1] + b1, 0.0f);
            hi.x = fmaxf(acc[mt][nt][2] + b0, 0.0f);
            hi.y = fmaxf(acc[mt][nt][3] + b1, 0.0f);
            *(float2*)&C[(size_t)r0 * 128 + cc]       = lo;
            *(float2*)&C[(size_t)(r0 + 8) * 128 + cc] = hi;
        }
    }
}

// QKV grid-fused: grid(3, M/128); blockIdx.x selects W/bias/dst. The three
// CTAs sharing blockIdx.y are adjacent in launch order -> co-resident -> A
// tile L2 reuse (A streamed from DRAM once, not 3x).
__global__ __launch_bounds__(256, 2)
void qkv_grid_kernel(const __nv_bfloat16* __restrict__ Ahi,
                     const __nv_bfloat16* __restrict__ Alo,
                     const __nv_bfloat16* __restrict__ whi,
                     const __nv_bfloat16* __restrict__ wlo,
                     const float* __restrict__ bq,
                     const float* __restrict__ bk,
                     const float* __restrict__ bv,
                     float* __restrict__ qo, float* __restrict__ ko,
                     float* __restrict__ vo)
{
    extern __shared__ __align__(16) char smc[];
    const uint32_t sb = smem_to_u32(smc);
    const int wsel = blockIdx.x;
    const int rowBase = blockIdx.y * 128;
    const __nv_bfloat16* Whi = whi + (size_t)wsel * 49152;
    const __nv_bfloat16* Wlo = wlo + (size_t)wsel * 49152;
    const float* bias = (wsel == 0) ? bq : (wsel == 1) ? bk : bv;
    float* dst        = (wsel == 0) ? qo : (wsel == 1) ? ko : vo;
    gemm_core(Ahi, Alo, 384, 384, rowBase, Whi, Wlo, bias, dst, smc, sb);
}

// Output projection (K = 128)
__global__ __launch_bounds__(256, 2)
void gemm_ps_kernel(const __nv_bfloat16* __restrict__ Ahi,
                    const __nv_bfloat16* __restrict__ Alo,
                    int lda, int K,
                    const __nv_bfloat16* __restrict__ Whi,
                    const __nv_bfloat16* __restrict__ Wlo,
                    const float* __restrict__ bias, float* __restrict__ C)
{
    extern __shared__ __align__(16) char smc[];
    const uint32_t sb = smem_to_u32(smc);
    gemm_core(Ahi, Alo, lda, K, blockIdx.x * 128, Whi, Wlo, bias, C, smc, sb);
}

// ===========================================================================
// Attention v5 (round-7 version, unchanged)
// ===========================================================================
#define KLD 520
#define VLD 24
#define KT_BYTES (16 * KLD * 2)
#define VS_BYTES (NSEQ * VLD * 2)
#define OFF_KT_HI 0
#define OFF_KT_LO (OFF_KT_HI + KT_BYTES)
#define OFF_VS_HI (OFF_KT_LO + KT_BYTES)
#define OFF_VS_LO (OFF_VS_HI + VS_BYTES)
#define OFF_OBUF  (OFF_VS_LO + VS_BYTES)
#define OFF_RED   (OFF_OBUF + 4 * 32 * 16 * 4)
#define ATTN_SMEM (OFF_RED + 4 * 32 * 8)

__global__ __launch_bounds__(256, 2)
void attn_tc_kernel(const float* __restrict__ q, const float* __restrict__ k,
                    const float* __restrict__ v,
                    __nv_bfloat16* __restrict__ ohi,
                    __nv_bfloat16* __restrict__ olo)
{
    extern __shared__ __align__(16) char smc[];
    const uint32_t sb = smem_to_u32(smc);
    __nv_bfloat16* kt_hi = (__nv_bfloat16*)(smc + OFF_KT_HI);
    __nv_bfloat16* kt_lo = (__nv_bfloat16*)(smc + OFF_KT_LO);
    __half*        vs_hi = (__half*)(smc + OFF_VS_HI);
    __half*        vs_lo = (__half*)(smc + OFF_VS_LO);
    float*  obuf   = (float*)(smc + OFF_OBUF);
    float2* redbuf = (float2*)(smc + OFF_RED);

    const int bt   = blockIdx.x;
    const int h    = blockIdx.y;
    const int tid  = threadIdx.x;
    const int warp = tid >> 5;
    const int lane = tid & 31;
    const int wm   = warp & 1;
    const int wn   = warp >> 1;
    const size_t base = (size_t)bt * NSEQ * DMODEL + h * DHEAD;

    for (int idx = tid; idx < NSEQ * 8; idx += 256) {
        const int m = idx >> 3, dp = (idx & 7) * 2;
        const float2 kv = *(const float2*)&k[base + (size_t)m * DMODEL + dp];
        uint32_t kh, kl;
        split2(kv.x, kv.y, kh, kl);
        kt_hi[dp * KLD + m] = __ushort_as_bfloat16((unsigned short)(kh & 0xffffu));
        kt_hi[(dp + 1) * KLD + m] = __ushort_as_bfloat16((unsigned short)(kh >> 16));
        kt_lo[dp * KLD + m] = __ushort_as_bfloat16((unsigned short)(kl & 0xffffu));
        kt_lo[(dp + 1) * KLD + m] = __ushort_as_bfloat16((unsigned short)(kl >> 16));

        const float2 vv = *(const float2*)&v[base + (size_t)m * DMODEL + dp];
        uint32_t vhi, vlo;
        splitH2(vv.x, vv.y, vhi, vlo);
        *(uint32_t*)&vs_hi[m * VLD + dp] = vhi;
        *(uint32_t*)&vs_lo[m * VLD + dp] = vlo;
    }
    __syncthreads();

    const int lq = lane >> 2;
    const int lc = lane & 3;

    for (int t0 = 0; t0 < NSEQ; t0 += 32) {
        uint32_t qh[4], ql[4];
        {
            const float* qrow = q + base + (size_t)(t0 + wm * 16 + lq) * DMODEL;
            const float2 x0 = *(const float2*)&qrow[2 * lc];
            const float2 x1 = *(const float2*)&qrow[8 + 2 * lc];
            const float2 y0 = *(const float2*)&qrow[8 * DMODEL + 2 * lc];
            const float2 y1 = *(const float2*)&qrow[8 * DMODEL + 8 + 2 * lc];
            split2(0.25f * x0.x, 0.25f * x0.y, qh[0], ql[0]);
            split2(0.25f * y0.x, 0.25f * y0.y, qh[1], ql[1]);
            split2(0.25f * x1.x, 0.25f * x1.y, qh[2], ql[2]);
            split2(0.25f * y1.x, 0.25f * y1.y, qh[3], ql[3]);
        }

        float sacc[16][4];
#pragma unroll
        for (int nt = 0; nt < 16; nt++)
#pragma unroll
            for (int e = 0; e < 4; e++) sacc[nt][e] = 0.0f;

#pragma unroll
        for (int np = 0; np < 8; np++) {
            const int key0 = wn * 128 + np * 16;
            const uint32_t kaddr =
                sb + OFF_KT_HI + ((lane & 15) * KLD + key0 + (lane >> 4) * 8) * 2;
            uint32_t bh[4], bl[4];
            ldsm_x4t(bh, kaddr);
            ldsm_x4t(bl, kaddr + KT_BYTES);
#pragma unroll
            for (int sub = 0; sub < 2; sub++) {
                const int nt = np * 2 + sub;
                mma_bf16(sacc[nt], qh, bh[2 * sub], bh[2 * sub + 1]);
                mma_bf16(sacc[nt], qh, bl[2 * sub], bl[2 * sub + 1]);
                mma_bf16(sacc[nt], ql, bh[2 * sub], bh[2 * sub + 1]);
            }
        }

        float m0 = -1e30f, m1 = -1e30f;
#pragma unroll
        for (int nt = 0; nt < 16; nt++) {
            m0 = fmaxf(m0, fmaxf(sacc[nt][0], sacc[nt][1]));
            m1 = fmaxf(m1, fmaxf(sacc[nt][2], sacc[nt][3]));
        }
        m0 = fmaxf(m0, __shfl_xor_sync(0xffffffffu, m0, 1));
        m0 = fmaxf(m0, __shfl_xor_sync(0xffffffffu, m0, 2));
        m1 = fmaxf(m1, __shfl_xor_sync(0xffffffffu, m1, 1));
        m1 = fmaxf(m1, __shfl_xor_sync(0xffffffffu, m1, 2));

        float s0 = 0.0f, s1 = 0.0f;
#pragma unroll
        for (int nt = 0; nt < 16; nt++) {
            sacc[nt][0] = __expf(sacc[nt][0] - m0); s0 += sacc[nt][0];
            sacc[nt][1] = __expf(sacc[nt][1] - m0); s0 += sacc[nt][1];
            sacc[nt][2] = __expf(sacc[nt][2] - m1); s1 += sacc[nt][2];
            sacc[nt][3] = __expf(sacc[nt][3] - m1); s1 += sacc[nt][3];
        }
        s0 += __shfl_xor_sync(0xffffffffu, s0, 1);
        s0 += __shfl_xor_sync(0xffffffffu, s0, 2);
        s1 += __shfl_xor_sync(0xffffffffu, s1, 1);
        s1 += __shfl_xor_sync(0xffffffffu, s1, 2);

        if (lc == 0) {
            redbuf[wn * 32 + wm * 16 + lq]     = make_float2(m0, s0);
            redbuf[wn * 32 + wm * 16 + lq + 8] = make_float2(m1, s1);
        }
        __syncthreads();

        float scale0, scale1;
        {
            float M0 = -1e30f, M1 = -1e30f;
#pragma unroll
            for (int w = 0; w < 4; w++) {
                M0 = fmaxf(M0, redbuf[w * 32 + wm * 16 + lq].x);
                M1 = fmaxf(M1, redbuf[w * 32 + wm * 16 + lq + 8].x);
            }
            float t0v = 0.0f, t1v = 0.0f;
#pragma unroll
            for (int w = 0; w < 4; w++) {
                const float2 p0 = redbuf[w * 32 + wm * 16 + lq];
                const float2 p1 = redbuf[w * 32 + wm * 16 + lq + 8];
                t0v += __expf(p0.x - M0) * p0.y;
                t1v += __expf(p1.x - M1) * p1.y;
            }
            scale0 = __expf(m0 - M0) / t0v;
            scale1 = __expf(m1 - M1) / t1v;
        }

        float ohh[2][4], ohl[2][4];
#pragma unroll
        for (int sub = 0; sub < 2; sub++)
#pragma unroll
            for (int e = 0; e < 4; e++) { ohh[sub][e] = 0.0f; ohl[sub][e] = 0.0f; }

#pragma unroll
        for (int t = 0; t < 8; t++) {
            uint32_t ph[4];
            ph[0] = packh2(sacc[2*t][0]   * scale0, sacc[2*t][1]   * scale0);
            ph[1] = packh2(sacc[2*t][2]   * scale1, sacc[2*t][3]   * scale1);
            ph[2] = packh2(sacc[2*t+1][0] * scale0, sacc[2*t+1][1] * scale0);
            ph[3] = packh2(sacc[2*t+1][2] * scale1, sacc[2*t+1][3] * scale1);

            const int key0 = wn * 128 + t * 16;
            const uint32_t vaddr =
                sb + OFF_VS_HI + ((key0 + (lane & 15)) * VLD + (lane >> 4) * 8) * 2;
            uint32_t vh[4], vl[4];
            ldsm_x4t(vh, vaddr);
            ldsm_x4t(vl, vaddr + VS_BYTES);
#pragma unroll
            for (int sub = 0; sub < 2; sub++) {
                mma_f16(ohh[sub], ph, vh[2 * sub], vh[2 * sub + 1]);
                mma_f16(ohl[sub], ph, vl[2 * sub], vl[2 * sub + 1]);
            }
        }

        {
            float* ob = obuf + wn * 512;
            const int r0 = wm * 16 + lq;
#pragma unroll
            for (int sub = 0; sub < 2; sub++) {
                const int d0 = sub * 8 + 2 * lc;
                float2 a, b;
                a.x = ohh[sub][0] + ohl[sub][0];
                a.y = ohh[sub][1] + ohl[sub][1];
                b.x = ohh[sub][2] + ohl[sub][2];
                b.y = ohh[sub][3] + ohl[sub][3];
                *(float2*)&ob[r0 * 16 + d0]       = a;
                *(float2*)&ob[(r0 + 8) * 16 + d0] = b;
            }
        }
        __syncthreads();
        if (tid < 128) {
            const int q4  = tid * 4;
            const int row = q4 >> 4;
            const int d0  = q4 & 15;
            const float4 a = *(const float4*)&obuf[row * 16 + d0];
            const float4 b = *(const float4*)&obuf[512 + row * 16 + d0];
            const float4 c = *(const float4*)&obuf[1024 + row * 16 + d0];
            const float4 d = *(const float4*)&obuf[1536 + row * 16 + d0];
            float4 r;
            r.x = a.x + b.x + c.x + d.x;
            r.y = a.y + b.y + c.y + d.y;
            r.z = a.z + b.z + c.z + d.z;
            r.w = a.w + b.w + c.w + d.w;
            uint32_t h0, l0, h1, l1;
            split2(r.x, r.y, h0, l0);
            split2(r.z, r.w, h1, l1);
            const size_t go = base + (size_t)(t0 + row) * DMODEL + d0;
            *(uint2*)&ohi[go] = make_uint2(h0, h1);
            *(uint2*)&olo[go] = make_uint2(l0, l1);
        }
        __syncthreads();
    }
}

// ===========================================================================
extern "C" void kernel_launch(void* const* d_in, const int* in_sizes, int n_in,
                              void* d_out, int out_size)
{
    const float* X   = (const float*)d_in[0];
    const float* STE = (const float*)d_in[1];
    const float* Wq  = (const float*)d_in[2];
    const float* bq  = (const float*)d_in[3];
    const float* Wk  = (const float*)d_in[4];
    const float* bk  = (const float*)d_in[5];
    const float* Wv  = (const float*)d_in[6];
    const float* bv  = (const float*)d_in[7];
    const float* Wo  = (const float*)d_in[8];
    const float* bo  = (const float*)d_in[9];
    float* out = (float*)d_out;

    const int M  = in_sizes[0] / DMODEL;   // 49152
    const int BT = M / NSEQ;               // 96

    float *q, *k, *v;
    __nv_bfloat16 *ahi, *alo, *whi, *wlo, *ohi, *olo;
    cudaGetSymbolAddress((void**)&q,   g_q);
    cudaGetSymbolAddress((void**)&k,   g_k);
    cudaGetSymbolAddress((void**)&v,   g_v);
    cudaGetSymbolAddress((void**)&ahi, g_ahi);
    cudaGetSymbolAddress((void**)&alo, g_alo);
    cudaGetSymbolAddress((void**)&whi, g_whi);
    cudaGetSymbolAddress((void**)&wlo, g_wlo);
    cudaGetSymbolAddress((void**)&ohi, g_ohi);
    cudaGetSymbolAddress((void**)&olo, g_olo);

    presplit_x_kernel<<<4608, 256>>>(X, STE, M, ahi, alo);
    presplit_w_kernel<<<160, 256>>>(Wq, Wk, Wv, Wo, whi, wlo);

    cudaFuncSetAttribute(qkv_grid_kernel, cudaFuncAttributeMaxDynamicSharedMemorySize,
                         GEMM_SMEM);
    qkv_grid_kernel<<<dim3(3, M / 128), 256, GEMM_SMEM>>>(
        ahi, alo, whi, wlo, bq, bk, bv, q, k, v);

    cudaFuncSetAttribute(attn_tc_kernel, cudaFuncAttributeMaxDynamicSharedMemorySize,
                         ATTN_SMEM);
    attn_tc_kernel<<<dim3(BT, KHEADS), 256, ATTN_SMEM>>>(q, k, v, ohi, olo);

    cudaFuncSetAttribute(gemm_ps_kernel, cudaFuncAttributeMaxDynamicSharedMemorySize,
                         GEMM_SMEM);
    gemm_ps_kernel<<<M / 128, 256, GEMM_SMEM>>>(ohi, olo, 128, 128,
                                                whi + WOFF_O, wlo + WOFF_O, bo, out);
}

// round 13
// speedup vs baseline: 1.4632x; 1.4632x over previous
#include <cuda_runtime.h>
#include <cuda_bf16.h>
#include <cuda_fp16.h>
#include <cstdint>

// Problem constants: B=8, T=12, N=512, D_MODEL=128, K_HEADS=8, D_HEAD=16.
#define DMODEL   128
#define KHEADS   8
#define DHEAD    16
#define NSEQ     512
#define MMAX     49152

// ---------------- generic-ISA tensor helpers (compute_103-safe) ------------
__device__ __forceinline__ uint32_t smem_to_u32(const void* p) {
    uint32_t a;
    asm("{ .reg .u64 t; cvta.to.shared.u64 t, %1; cvt.u32.u64 %0, t; }"
        : "=r"(a) : "l"(p));
    return a;
}
__device__ __forceinline__ void ldsm_x4(uint32_t* r, uint32_t addr) {
    asm volatile("ldmatrix.sync.aligned.m8n8.x4.shared.b16 {%0,%1,%2,%3}, [%4];"
                 : "=r"(r[0]), "=r"(r[1]), "=r"(r[2]), "=r"(r[3]) : "r"(addr));
}
__device__ __forceinline__ void ldsm_x4t(uint32_t* r, uint32_t addr) {
    asm volatile("ldmatrix.sync.aligned.m8n8.x4.trans.shared.b16 {%0,%1,%2,%3}, [%4];"
                 : "=r"(r[0]), "=r"(r[1]), "=r"(r[2]), "=r"(r[3]) : "r"(addr));
}
__device__ __forceinline__ void mma_bf16(float* d, const uint32_t* a,
                                         uint32_t b0, uint32_t b1) {
    asm volatile("mma.sync.aligned.m16n8k16.row.col.f32.bf16.bf16.f32 "
                 "{%0,%1,%2,%3}, {%4,%5,%6,%7}, {%8,%9}, {%0,%1,%2,%3};"
                 : "+f"(d[0]), "+f"(d[1]), "+f"(d[2]), "+f"(d[3])
                 : "r"(a[0]), "r"(a[1]), "r"(a[2]), "r"(a[3]), "r"(b0), "r"(b1));
}
__device__ __forceinline__ void mma_f16(float* d, const uint32_t* a,
                                        uint32_t b0, uint32_t b1) {
    asm volatile("mma.sync.aligned.m16n8k16.row.col.f32.f16.f16.f32 "
                 "{%0,%1,%2,%3}, {%4,%5,%6,%7}, {%8,%9}, {%0,%1,%2,%3};"
                 : "+f"(d[0]), "+f"(d[1]), "+f"(d[2]), "+f"(d[3])
                 : "r"(a[0]), "r"(a[1]), "r"(a[2]), "r"(a[3]), "r"(b0), "r"(b1));
}
#define CP_ASYNC16(dst_u32, src_ptr) \
    asm volatile("cp.async.ca.shared.global [%0], [%1], 16;" \
                 :: "r"(dst_u32), "l"(src_ptr))
#define CP_COMMIT() asm volatile("cp.async.commit_group;" ::: "memory")
#define CP_WAIT(n)  asm volatile("cp.async.wait_group %0;" :: "n"(n) : "memory")

// cheap split: packed cvt + shift-unpack (bf16->f32 is a 16-bit shift)
__device__ __forceinline__ void split2(float x, float y, uint32_t& hi, uint32_t& lo) {
    uint32_t h;
    asm("cvt.rn.bf16x2.f32 %0, %1, %2;" : "=r"(h) : "f"(y), "f"(x));
    const float hx = __uint_as_float(h << 16);
    const float hy = __uint_as_float(h & 0xffff0000u);
    uint32_t l;
    asm("cvt.rn.bf16x2.f32 %0, %1, %2;" : "=r"(l) : "f"(y - hy), "f"(x - hx));
    hi = h; lo = l;
}
__device__ __forceinline__ uint32_t packh2(float x, float y) {
    const half2 h = __floats2half2_rn(x, y);
    return *(const uint32_t*)&h;
}

// ---------------- scratch --------------------------------------------------
__device__ float g_q[(size_t)MMAX * DMODEL];
__device__ float g_k[(size_t)MMAX * DMODEL];
__device__ float g_v[(size_t)MMAX * DMODEL];
__device__ __nv_bfloat16 g_ahi[(size_t)MMAX * 384];
__device__ __nv_bfloat16 g_alo[(size_t)MMAX * 384];
__device__ __nv_bfloat16 g_ohi[(size_t)MMAX * DMODEL];
__device__ __nv_bfloat16 g_olo[(size_t)MMAX * DMODEL];
#define W_TOTAL (3 * 49152 + 16384)
__device__ __nv_bfloat16 g_whi[W_TOTAL];
__device__ __nv_bfloat16 g_wlo[W_TOTAL];
#define WOFF_Q 0
#define WOFF_K 49152
#define WOFF_V 98304
#define WOFF_O 147456

// ===========================================================================
// Pre-split kernels
// ===========================================================================
__global__ void presplit_x_kernel(const float* __restrict__ X,
                                  const float* __restrict__ STE, int M,
                                  __nv_bfloat16* __restrict__ ahi,
                                  __nv_bfloat16* __restrict__ alo)
{
    const int total = M * 96;
    for (int i = blockIdx.x * blockDim.x + threadIdx.x; i < total;
         i += gridDim.x * blockDim.x) {
        const int m = i / 96, c = (i % 96) * 4;
        const float4 x = (c < 128)
            ? *(const float4*)&X[(size_t)m * 128 + c]
            : *(const float4*)&STE[(size_t)m * 256 + (c - 128)];
        uint32_t h0, l0, h1, l1;
        split2(x.x, x.y, h0, l0);
        split2(x.z, x.w, h1, l1);
        *(uint2*)&ahi[(size_t)m * 384 + c] = make_uint2(h0, h1);
        *(uint2*)&alo[(size_t)m * 384 + c] = make_uint2(l0, l1);
    }
}

__global__ void presplit_w_kernel(const float* __restrict__ Wq,
                                  const float* __restrict__ Wk,
                                  const float* __restrict__ Wv,
                                  const float* __restrict__ Wo,
                                  __nv_bfloat16* __restrict__ whi,
                                  __nv_bfloat16* __restrict__ wlo)
{
    const int i = blockIdx.x * blockDim.x + threadIdx.x;
    if (i >= W_TOTAL / 4) return;
    const float* src; int off;
    if      (i < 12288) { src = Wq; off = 0; }
    else if (i < 24576) { src = Wk; off = 12288; }
    else if (i < 36864) { src = Wv; off = 24576; }
    else                { src = Wo; off = 36864; }
    const int j = (i - off) * 4;
    const float4 x = *(const float4*)&src[j];
    uint32_t h0, l0, h1, l1;
    split2(x.x, x.y, h0, l0);
    split2(x.z, x.w, h1, l1);
    *(uint2*)&whi[off * 4 + j] = make_uint2(h0, h1);
    *(uint2*)&wlo[off * 4 + j] = make_uint2(l0, l1);
}

// ===========================================================================
// Pipelined mma.sync GEMM (round-9 proven): C = relu(A @ W + b)
// cp.async 2-stage double buffering, K-chunks of 32, occupancy 2.
// ===========================================================================
#define GK      32
#define GA_LD   40
#define GB_LD   136
#define GA_BUF  (128 * GA_LD * 2)
#define GB_BUF  (GK * GB_LD * 2)
#define GSM_A   0
#define GSM_B   (4 * GA_BUF)
#define GEMM_SMEM (GSM_B + 4 * GB_BUF)   // 75776

__global__ __launch_bounds__(256, 2)
void gemm_ps_kernel(const __nv_bfloat16* __restrict__ Ahi,
                    const __nv_bfloat16* __restrict__ Alo,
                    int lda, int K,
                    const __nv_bfloat16* __restrict__ Whi,
                    const __nv_bfloat16* __restrict__ Wlo,
                    const float* __restrict__ bias, float* __restrict__ C)
{
    extern __shared__ __align__(16) char smc[];
    const uint32_t sb = smem_to_u32(smc);
    const int tid  = threadIdx.x;
    const int warp = tid >> 5;
    const int lane = tid & 31;
    const int wm   = warp & 3;
    const int wn   = warp >> 2;
    const int rowBase = blockIdx.x * 128;

    float acc[2][8][4];
#pragma unroll
    for (int mt = 0; mt < 2; mt++)
#pragma unroll
        for (int nt = 0; nt < 8; nt++)
#pragma unroll
            for (int e = 0; e < 4; e++) acc[mt][nt][e] = 0.0f;

    const int nChunks = K / GK;

    auto load_chunk = [&](int c, int buf) {
        const int k0 = c * GK;
        {
            const int r = tid >> 1;
#pragma unroll
            for (int hl = 0; hl < 2; hl++) {
                const __nv_bfloat16* gsrc =
                    (hl ? Alo : Ahi) + (size_t)(rowBase + r) * lda + k0;
                const uint32_t dbase =
                    sb + GSM_A + (buf * 2 + hl) * GA_BUF + r * (GA_LD * 2);
#pragma unroll
                for (int s2 = 0; s2 < 2; s2++) {
                    const int s = (tid & 1) * 2 + s2;
                    CP_ASYNC16(dbase + s * 16, gsrc + s * 8);
                }
            }
        }
        {
            const int kk = tid >> 3;
#pragma unroll
            for (int hl = 0; hl < 2; hl++) {
                const __nv_bfloat16* gsrc =
                    (hl ? Wlo : Whi) + (size_t)(k0 + kk) * 128;
                const uint32_t dbase =
                    sb + GSM_B + (buf * 2 + hl) * GB_BUF + kk * (GB_LD * 2);
#pragma unroll
                for (int s2 = 0; s2 < 2; s2++) {
                    const int s = (tid & 7) * 2 + s2;
                    CP_ASYNC16(dbase + s * 16, gsrc + s * 8);
                }
            }
        }
        CP_COMMIT();
    };

    load_chunk(0, 0);

    for (int c = 0; c < nChunks; c++) {
        if (c + 1 < nChunks) { load_chunk(c + 1, (c + 1) & 1); CP_WAIT(1); }
        else                 { CP_WAIT(0); }
        __syncthreads();

        const int buf = c & 1;
        const uint32_t abase_h = sb + GSM_A + (buf * 2 + 0) * GA_BUF;
        const uint32_t abase_l = sb + GSM_A + (buf * 2 + 1) * GA_BUF;
        const uint32_t bbase_h = sb + GSM_B + (buf * 2 + 0) * GB_BUF;
        const uint32_t bbase_l = sb + GSM_B + (buf * 2 + 1) * GB_BUF;

#pragma unroll
        for (int ks = 0; ks < 2; ks++) {
            uint32_t ah[2][4], al[2][4];
            const int arow = lane & 15;
            const int acol = ks * 16 + (lane >> 4) * 8;
#pragma unroll
            for (int mt = 0; mt < 2; mt++) {
                const uint32_t aoff =
                    ((wm * 32 + mt * 16 + arow) * GA_LD + acol) * 2;
                ldsm_x4(ah[mt], abase_h + aoff);
                ldsm_x4(al[mt], abase_l + aoff);
            }
            const int brow = ks * 16 + (lane & 15);
#pragma unroll
            for (int np = 0; np < 4; np++) {
                const uint32_t boff =
                    (brow * GB_LD + wn * 64 + np * 16 + (lane >> 4) * 8) * 2;
                uint32_t bh[4], bl[4];
                ldsm_x4t(bh, bbase_h + boff);
                ldsm_x4t(bl, bbase_l + boff);
#pragma unroll
                for (int sub = 0; sub < 2; sub++) {
                    const int nt = np * 2 + sub;
#pragma unroll
                    for (int mt = 0; mt < 2; mt++) {
                        mma_bf16(acc[mt][nt], ah[mt], bh[2 * sub], bh[2 * sub + 1]);
                        mma_bf16(acc[mt][nt], ah[mt], bl[2 * sub], bl[2 * sub + 1]);
                        mma_bf16(acc[mt][nt], al[mt], bh[2 * sub], bh[2 * sub + 1]);
                    }
                }
            }
        }
        __syncthreads();
    }

#pragma unroll
    for (int mt = 0; mt < 2; mt++) {
        const int r0 = rowBase + wm * 32 + mt * 16 + (lane >> 2);
#pragma unroll
        for (int nt = 0; nt < 8; nt++) {
            const int cc = wn * 64 + nt * 8 + (lane & 3) * 2;
            const float b0 = bias[cc], b1 = bias[cc + 1];
            float2 lo, hi;
            lo.x = fmaxf(acc[mt][nt][0] + b0, 0.0f);
            lo.y = fmaxf(acc[mt][nt][1] + b1, 0.0f);
            hi.x = fmaxf(acc[mt][nt][2] + b0, 0.0f);
            hi.y = fmaxf(acc[mt][nt][3] + b1, 0.0f);
            *(float2*)&C[(size_t)r0 * 128 + cc]       = lo;
            *(float2*)&C[(size_t)(r0 + 8) * 128 + cc] = hi;
        }
    }
}

// ===========================================================================
// Attention v6: S = 3-term bf16 (unchanged); softmax in log2 domain
// (Q pre-scaled by 0.25*log2e, exp2f everywhere — saves the FMUL in every
// exp); PV = single-fp16 P x single-fp16 V (one mma chain). O pre-split.
// ===========================================================================
#define KLD 520
#define VLD 24
#define KT_BYTES (16 * KLD * 2)
#define VS_BYTES (NSEQ * VLD * 2)
#define OFF_KT_HI 0
#define OFF_KT_LO (OFF_KT_HI + KT_BYTES)
#define OFF_VS    (OFF_KT_LO + KT_BYTES)
#define OFF_OBUF  (OFF_VS + VS_BYTES)
#define OFF_RED   (OFF_OBUF + 4 * 32 * 16 * 4)
#define ATTN_SMEM (OFF_RED + 4 * 32 * 8)          // 67072 bytes

#define QSCALE 0.3606737602f    /* 0.25 * log2(e) */

__global__ __launch_bounds__(256, 2)
void attn_tc_kernel(const float* __restrict__ q, const float* __restrict__ k,
                    const float* __restrict__ v,
                    __nv_bfloat16* __restrict__ ohi,
                    __nv_bfloat16* __restrict__ olo)
{
    extern __shared__ __align__(16) char smc[];
    const uint32_t sb = smem_to_u32(smc);
    __nv_bfloat16* kt_hi = (__nv_bfloat16*)(smc + OFF_KT_HI);
    __nv_bfloat16* kt_lo = (__nv_bfloat16*)(smc + OFF_KT_LO);
    __half*        vs    = (__half*)(smc + OFF_VS);
    float*  obuf   = (float*)(smc + OFF_OBUF);
    float2* redbuf = (float2*)(smc + OFF_RED);

    const int bt   = blockIdx.x;
    const int h    = blockIdx.y;
    const int tid  = threadIdx.x;
    const int warp = tid >> 5;
    const int lane = tid & 31;
    const int wm   = warp & 1;
    const int wn   = warp >> 1;
    const size_t base = (size_t)bt * NSEQ * DMODEL + h * DHEAD;

    // ---- stage K^T (bf16 hi/lo) and V (single fp16)
    for (int idx = tid; idx < NSEQ * 8; idx += 256) {
        const int m = idx >> 3, dp = (idx & 7) * 2;
        const float2 kv = *(const float2*)&k[base + (size_t)m * DMODEL + dp];
        uint32_t kh, kl;
        split2(kv.x, kv.y, kh, kl);
        kt_hi[dp * KLD + m] = __ushort_as_bfloat16((unsigned short)(kh & 0xffffu));
        kt_hi[(dp + 1) * KLD + m] = __ushort_as_bfloat16((unsigned short)(kh >> 16));
        kt_lo[dp * KLD + m] = __ushort_as_bfloat16((unsigned short)(kl & 0xffffu));
        kt_lo[(dp + 1) * KLD + m] = __ushort_as_bfloat16((unsigned short)(kl >> 16));

        const float2 vv = *(const float2*)&v[base + (size_t)m * DMODEL + dp];
        *(uint32_t*)&vs[m * VLD + dp] = packh2(vv.x, vv.y);
    }
    __syncthreads();

    const int lq = lane >> 2;
    const int lc = lane & 3;

    for (int t0 = 0; t0 < NSEQ; t0 += 32) {
        // ---- Q fragment, scaled by 0.25*log2e, split bf16
        uint32_t qh[4], ql[4];
        {
            const float* qrow = q + base + (size_t)(t0 + wm * 16 + lq) * DMODEL;
            const float2 x0 = *(const float2*)&qrow[2 * lc];
            const float2 x1 = *(const float2*)&qrow[8 + 2 * lc];
            const float2 y0 = *(const float2*)&qrow[8 * DMODEL + 2 * lc];
            const float2 y1 = *(const float2*)&qrow[8 * DMODEL + 8 + 2 * lc];
            split2(QSCALE * x0.x, QSCALE * x0.y, qh[0], ql[0]);
            split2(QSCALE * y0.x, QSCALE * y0.y, qh[1], ql[1]);
            split2(QSCALE * x1.x, QSCALE * x1.y, qh[2], ql[2]);
            split2(QSCALE * y1.x, QSCALE * y1.y, qh[3], ql[3]);
        }

        // ---- S' = (Q K^T) * log2e/4 : 16 rows x 128 keys
        float sacc[16][4];
#pragma unroll
        for (int nt = 0; nt < 16; nt++)
#pragma unroll
            for (int e = 0; e < 4; e++) sacc[nt][e] = 0.0f;

#pragma unroll
        for (int np = 0; np < 8; np++) {
            const int key0 = wn * 128 + np * 16;
            const uint32_t kaddr =
                sb + OFF_KT_HI + ((lane & 15) * KLD + key0 + (lane >> 4) * 8) * 2;
            uint32_t bh[4], bl[4];
            ldsm_x4t(bh, kaddr);
            ldsm_x4t(bl, kaddr + KT_BYTES);
#pragma unroll
            for (int sub = 0; sub < 2; sub++) {
                const int nt = np * 2 + sub;
                mma_bf16(sacc[nt], qh, bh[2 * sub], bh[2 * sub + 1]);
                mma_bf16(sacc[nt], qh, bl[2 * sub], bl[2 * sub + 1]);
                mma_bf16(sacc[nt], ql, bh[2 * sub], bh[2 * sub + 1]);
            }
        }

        // ---- local log2-domain softmax stats, exp2 in place
        float m0 = -1e30f, m1 = -1e30f;
#pragma unroll
        for (int nt = 0; nt < 16; nt++) {
            m0 = fmaxf(m0, fmaxf(sacc[nt][0], sacc[nt][1]));
            m1 = fmaxf(m1, fmaxf(sacc[nt][2], sacc[nt][3]));
        }
        m0 = fmaxf(m0, __shfl_xor_sync(0xffffffffu, m0, 1));
        m0 = fmaxf(m0, __shfl_xor_sync(0xffffffffu, m0, 2));
        m1 = fmaxf(m1, __shfl_xor_sync(0xffffffffu, m1, 1));
        m1 = fmaxf(m1, __shfl_xor_sync(0xffffffffu, m1, 2));

        float s0 = 0.0f, s1 = 0.0f;
#pragma unroll
        for (int nt = 0; nt < 16; nt++) {
            sacc[nt][0] = exp2f(sacc[nt][0] - m0); s0 += sacc[nt][0];
            sacc[nt][1] = exp2f(sacc[nt][1] - m0); s0 += sacc[nt][1];
            sacc[nt][2] = exp2f(sacc[nt][2] - m1); s1 += sacc[nt][2];
            sacc[nt][3] = exp2f(sacc[nt][3] - m1); s1 += sacc[nt][3];
        }
        s0 += __shfl_xor_sync(0xffffffffu, s0, 1);
        s0 += __shfl_xor_sync(0xffffffffu, s0, 2);
        s1 += __shfl_xor_sync(0xffffffffu, s1, 1);
        s1 += __shfl_xor_sync(0xffffffffu, s1, 2);

        if (lc == 0) {
            redbuf[wn * 32 + wm * 16 + lq]     = make_float2(m0, s0);
            redbuf[wn * 32 + wm * 16 + lq + 8] = make_float2(m1, s1);
        }
        __syncthreads();

        // combine across 4 n-warps (log2 domain)
        float scale0, scale1;
        {
            float M0 = -1e30f, M1 = -1e30f;
#pragma unroll
            for (int w = 0; w < 4; w++) {
                M0 = fmaxf(M0, redbuf[w * 32 + wm * 16 + lq].x);
                M1 = fmaxf(M1, redbuf[w * 32 + wm * 16 + lq + 8].x);
            }
            float t0v = 0.0f, t1v = 0.0f;
#pragma unroll
            for (int w = 0; w < 4; w++) {
                const float2 p0 = redbuf[w * 32 + wm * 16 + lq];
                const float2 p1 = redbuf[w * 32 + wm * 16 + lq + 8];
                t0v += exp2f(p0.x - M0) * p0.y;
                t1v += exp2f(p1.x - M1) * p1.y;
            }
            scale0 = exp2f(m0 - M0) / t0v;
            scale1 = exp2f(m1 - M1) / t1v;
        }

        // ---- O partial = P V : single fp16 x fp16 chain
        float oac[2][4];
#pragma unroll
        for (int sub = 0; sub < 2; sub++)
#pragma unroll
            for (int e = 0; e < 4; e++) oac[sub][e] = 0.0f;

#pragma unroll
        for (int t = 0; t < 8; t++) {
            uint32_t ph[4];
            ph[0] = packh2(sacc[2*t][0]   * scale0, sacc[2*t][1]   * scale0);
            ph[1] = packh2(sacc[2*t][2]   * scale1, sacc[2*t][3]   * scale1);
            ph[2] = packh2(sacc[2*t+1][0] * scale0, sacc[2*t+1][1] * scale0);
            ph[3] = packh2(sacc[2*t+1][2] * scale1, sacc[2*t+1][3] * scale1);

            const int key0 = wn * 128 + t * 16;
            const uint32_t vaddr =
                sb + OFF_VS + ((key0 + (lane & 15)) * VLD + (lane >> 4) * 8) * 2;
            uint32_t vh[4];
            ldsm_x4t(vh, vaddr);
#pragma unroll
            for (int sub = 0; sub < 2; sub++)
                mma_f16(oac[sub], ph, vh[2 * sub], vh[2 * sub + 1]);
        }

        // ---- per-warp O partial to obuf, reduce over 4 n-warps, store split
        {
            float* ob = obuf + wn * 512;
            const int r0 = wm * 16 + lq;
#pragma unroll
            for (int sub = 0; sub < 2; sub++) {
                const int d0 = sub * 8 + 2 * lc;
                *(float2*)&ob[r0 * 16 + d0] =
                    make_float2(oac[sub][0], oac[sub][1]);
                *(float2*)&ob[(r0 + 8) * 16 + d0] =
                    make_float2(oac[sub][2], oac[sub][3]);
            }
        }
        __syncthreads();
        if (tid < 128) {
            const int q4  = tid * 4;
            const int row = q4 >> 4;
            const int d0  = q4 & 15;
            const float4 a = *(const float4*)&obuf[row * 16 + d0];
            const float4 b = *(const float4*)&obuf[512 + row * 16 + d0];
            const float4 c = *(const float4*)&obuf[1024 + row * 16 + d0];
            const float4 d = *(const float4*)&obuf[1536 + row * 16 + d0];
            float4 r;
            r.x = a.x + b.x + c.x + d.x;
            r.y = a.y + b.y + c.y + d.y;
            r.z = a.z + b.z + c.z + d.z;
            r.w = a.w + b.w + c.w + d.w;
            uint32_t h0, l0, h1, l1;
            split2(r.x, r.y, h0, l0);
            split2(r.z, r.w, h1, l1);
            const size_t go = base + (size_t)(t0 + row) * DMODEL + d0;
            *(uint2*)&ohi[go] = make_uint2(h0, h1);
            *(uint2*)&olo[go] = make_uint2(l0, l1);
        }
        __syncthreads();
    }
}

// ===========================================================================
extern "C" void kernel_launch(void* const* d_in, const int* in_sizes, int n_in,
                              void* d_out, int out_size)
{
    const float* X   = (const float*)d_in[0];
    const float* STE = (const float*)d_in[1];
    const float* Wq  = (const float*)d_in[2];
    const float* bq  = (const float*)d_in[3];
    const float* Wk  = (const float*)d_in[4];
    const float* bk  = (const float*)d_in[5];
    const float* Wv  = (const float*)d_in[6];
    const float* bv  = (const float*)d_in[7];
    const float* Wo  = (const float*)d_in[8];
    const float* bo  = (const float*)d_in[9];
    float* out = (float*)d_out;

    const int M  = in_sizes[0] / DMODEL;   // 49152
    const int BT = M / NSEQ;               // 96

    float *q, *k, *v;
    __nv_bfloat16 *ahi, *alo, *whi, *wlo, *ohi, *olo;
    cudaGetSymbolAddress((void**)&q,   g_q);
    cudaGetSymbolAddress((void**)&k,   g_k);
    cudaGetSymbolAddress((void**)&v,   g_v);
    cudaGetSymbolAddress((void**)&ahi, g_ahi);
    cudaGetSymbolAddress((void**)&alo, g_alo);
    cudaGetSymbolAddress((void**)&whi, g_whi);
    cudaGetSymbolAddress((void**)&wlo, g_wlo);
    cudaGetSymbolAddress((void**)&ohi, g_ohi);
    cudaGetSymbolAddress((void**)&olo, g_olo);

    presplit_x_kernel<<<4608, 256>>>(X, STE, M, ahi, alo);
    presplit_w_kernel<<<160, 256>>>(Wq, Wk, Wv, Wo, whi, wlo);

    cudaFuncSetAttribute(gemm_ps_kernel, cudaFuncAttributeMaxDynamicSharedMemorySize,
                         GEMM_SMEM);
    const dim3 gproj(M / 128);
    gemm_ps_kernel<<<gproj, 256, GEMM_SMEM>>>(ahi, alo, 384, 384,
                                              whi + WOFF_Q, wlo + WOFF_Q, bq, q);
    gemm_ps_kernel<<<gproj, 256, GEMM_SMEM>>>(ahi, alo, 384, 384,
                                              whi + WOFF_K, wlo + WOFF_K, bk, k);
    gemm_ps_kernel<<<gproj, 256, GEMM_SMEM>>>(ahi, alo, 384, 384,
                                              whi + WOFF_V, wlo + WOFF_V, bv, v);

    cudaFuncSetAttribute(attn_tc_kernel, cudaFuncAttributeMaxDynamicSharedMemorySize,
                         ATTN_SMEM);
    attn_tc_kernel<<<dim3(BT, KHEADS), 256, ATTN_SMEM>>>(q, k, v, ohi, olo);

    gemm_ps_kernel<<<gproj, 256, GEMM_SMEM>>>(ohi, olo, 128, 128,
                                              whi + WOFF_O, wlo + WOFF_O, bo, out);
}

// round 14
// speedup vs baseline: 1.5630x; 1.0682x over previous
#include <cuda_runtime.h>
#include <cuda_bf16.h>
#include <cuda_fp16.h>
#include <cstdint>

// Problem constants: B=8, T=12, N=512, D_MODEL=128, K_HEADS=8, D_HEAD=16.
#define DMODEL   128
#define KHEADS   8
#define DHEAD    16
#define NSEQ     512
#define MMAX     49152

// ---------------- generic-ISA tensor helpers (compute_103-safe) ------------
__device__ __forceinline__ uint32_t smem_to_u32(const void* p) {
    uint32_t a;
    asm("{ .reg .u64 t; cvta.to.shared.u64 t, %1; cvt.u32.u64 %0, t; }"
        : "=r"(a) : "l"(p));
    return a;
}
__device__ __forceinline__ void ldsm_x4(uint32_t* r, uint32_t addr) {
    asm volatile("ldmatrix.sync.aligned.m8n8.x4.shared.b16 {%0,%1,%2,%3}, [%4];"
                 : "=r"(r[0]), "=r"(r[1]), "=r"(r[2]), "=r"(r[3]) : "r"(addr));
}
__device__ __forceinline__ void ldsm_x4t(uint32_t* r, uint32_t addr) {
    asm volatile("ldmatrix.sync.aligned.m8n8.x4.trans.shared.b16 {%0,%1,%2,%3}, [%4];"
                 : "=r"(r[0]), "=r"(r[1]), "=r"(r[2]), "=r"(r[3]) : "r"(addr));
}
__device__ __forceinline__ void mma_bf16(float* d, const uint32_t* a,
                                         uint32_t b0, uint32_t b1) {
    asm volatile("mma.sync.aligned.m16n8k16.row.col.f32.bf16.bf16.f32 "
                 "{%0,%1,%2,%3}, {%4,%5,%6,%7}, {%8,%9}, {%0,%1,%2,%3};"
                 : "+f"(d[0]), "+f"(d[1]), "+f"(d[2]), "+f"(d[3])
                 : "r"(a[0]), "r"(a[1]), "r"(a[2]), "r"(a[3]), "r"(b0), "r"(b1));
}
__device__ __forceinline__ void mma_f16(float* d, const uint32_t* a,
                                        uint32_t b0, uint32_t b1) {
    asm volatile("mma.sync.aligned.m16n8k16.row.col.f32.f16.f16.f32 "
                 "{%0,%1,%2,%3}, {%4,%5,%6,%7}, {%8,%9}, {%0,%1,%2,%3};"
                 : "+f"(d[0]), "+f"(d[1]), "+f"(d[2]), "+f"(d[3])
                 : "r"(a[0]), "r"(a[1]), "r"(a[2]), "r"(a[3]), "r"(b0), "r"(b1));
}
#define CP_ASYNC16(dst_u32, src_ptr) \
    asm volatile("cp.async.ca.shared.global [%0], [%1], 16;" \
                 :: "r"(dst_u32), "l"(src_ptr))
#define CP_COMMIT() asm volatile("cp.async.commit_group;" ::: "memory")
#define CP_WAIT(n)  asm volatile("cp.async.wait_group %0;" :: "n"(n) : "memory")

// cheap split: packed cvt + shift-unpack (bf16->f32 is a 16-bit shift)
__device__ __forceinline__ void split2(float x, float y, uint32_t& hi, uint32_t& lo) {
    uint32_t h;
    asm("cvt.rn.bf16x2.f32 %0, %1, %2;" : "=r"(h) : "f"(y), "f"(x));
    const float hx = __uint_as_float(h << 16);
    const float hy = __uint_as_float(h & 0xffff0000u);
    uint32_t l;
    asm("cvt.rn.bf16x2.f32 %0, %1, %2;" : "=r"(l) : "f"(y - hy), "f"(x - hx));
    hi = h; lo = l;
}
__device__ __forceinline__ uint32_t packh2(float x, float y) {
    const half2 h = __floats2half2_rn(x, y);
    return *(const uint32_t*)&h;
}

// ---------------- scratch --------------------------------------------------
__device__ float g_q[(size_t)MMAX * DMODEL];
__device__ float g_k[(size_t)MMAX * DMODEL];
__device__ float g_v[(size_t)MMAX * DMODEL];
__device__ __nv_bfloat16 g_ahi[(size_t)MMAX * 384];
__device__ __nv_bfloat16 g_alo[(size_t)MMAX * 384];
__device__ __nv_bfloat16 g_ohi[(size_t)MMAX * DMODEL];
__device__ __nv_bfloat16 g_olo[(size_t)MMAX * DMODEL];
#define W_TOTAL (3 * 49152 + 16384)
__device__ __nv_bfloat16 g_whi[W_TOTAL];
__device__ __nv_bfloat16 g_wlo[W_TOTAL];
#define WOFF_O 147456

// ===========================================================================
// Pre-split kernels
// ===========================================================================
__global__ void presplit_x_kernel(const float* __restrict__ X,
                                  const float* __restrict__ STE, int M,
                                  __nv_bfloat16* __restrict__ ahi,
                                  __nv_bfloat16* __restrict__ alo)
{
    const int total = M * 96;
    for (int i = blockIdx.x * blockDim.x + threadIdx.x; i < total;
         i += gridDim.x * blockDim.x) {
        const int m = i / 96, c = (i % 96) * 4;
        const float4 x = (c < 128)
            ? *(const float4*)&X[(size_t)m * 128 + c]
            : *(const float4*)&STE[(size_t)m * 256 + (c - 128)];
        uint32_t h0, l0, h1, l1;
        split2(x.x, x.y, h0, l0);
        split2(x.z, x.w, h1, l1);
        *(uint2*)&ahi[(size_t)m * 384 + c] = make_uint2(h0, h1);
        *(uint2*)&alo[(size_t)m * 384 + c] = make_uint2(l0, l1);
    }
}

__global__ void presplit_w_kernel(const float* __restrict__ Wq,
                                  const float* __restrict__ Wk,
                                  const float* __restrict__ Wv,
                                  const float* __restrict__ Wo,
                                  __nv_bfloat16* __restrict__ whi,
                                  __nv_bfloat16* __restrict__ wlo)
{
    const int i = blockIdx.x * blockDim.x + threadIdx.x;
    if (i >= W_TOTAL / 4) return;
    const float* src; int off;
    if      (i < 12288) { src = Wq; off = 0; }
    else if (i < 24576) { src = Wk; off = 12288; }
    else if (i < 36864) { src = Wv; off = 24576; }
    else                { src = Wo; off = 36864; }
    const int j = (i - off) * 4;
    const float4 x = *(const float4*)&src[j];
    uint32_t h0, l0, h1, l1;
    split2(x.x, x.y, h0, l0);
    split2(x.z, x.w, h1, l1);
    *(uint2*)&whi[off * 4 + j] = make_uint2(h0, h1);
    *(uint2*)&wlo[off * 4 + j] = make_uint2(l0, l1);
}

// ===========================================================================
// Pipelined mma.sync GEMM core: C = relu(A @ W + b)
// cp.async 2-stage double buffering, K-chunks of 32, occupancy 2.
// 8 warps: 4m x 2n; warp tile 32x64; acc[2][8][4] = 64 regs.
// ===========================================================================
#define GK      32
#define GA_LD   40
#define GB_LD   136
#define GA_BUF  (128 * GA_LD * 2)
#define GB_BUF  (GK * GB_LD * 2)
#define GSM_A   0
#define GSM_B   (4 * GA_BUF)
#define GEMM_SMEM (GSM_B + 4 * GB_BUF)   // 75776

__device__ __forceinline__ void gemm_core(
    const __nv_bfloat16* __restrict__ Ahi,
    const __nv_bfloat16* __restrict__ Alo,
    int lda, int K, int rowBase,
    const __nv_bfloat16* __restrict__ Whi,
    const __nv_bfloat16* __restrict__ Wlo,
    const float* __restrict__ bias, float* __restrict__ C,
    uint32_t sb)
{
    const int tid  = threadIdx.x;
    const int warp = tid >> 5;
    const int lane = tid & 31;
    const int wm   = warp & 3;
    const int wn   = warp >> 2;

    float acc[2][8][4];
#pragma unroll
    for (int mt = 0; mt < 2; mt++)
#pragma unroll
        for (int nt = 0; nt < 8; nt++)
#pragma unroll
            for (int e = 0; e < 4; e++) acc[mt][nt][e] = 0.0f;

    const int nChunks = K / GK;

    auto load_chunk = [&](int c, int buf) {
        const int k0 = c * GK;
        {
            const int r = tid >> 1;
#pragma unroll
            for (int hl = 0; hl < 2; hl++) {
                const __nv_bfloat16* gsrc =
                    (hl ? Alo : Ahi) + (size_t)(rowBase + r) * lda + k0;
                const uint32_t dbase =
                    sb + GSM_A + (buf * 2 + hl) * GA_BUF + r * (GA_LD * 2);
#pragma unroll
                for (int s2 = 0; s2 < 2; s2++) {
                    const int s = (tid & 1) * 2 + s2;
                    CP_ASYNC16(dbase + s * 16, gsrc + s * 8);
                }
            }
        }
        {
            const int kk = tid >> 3;
#pragma unroll
            for (int hl = 0; hl < 2; hl++) {
                const __nv_bfloat16* gsrc =
                    (hl ? Wlo : Whi) + (size_t)(k0 + kk) * 128;
                const uint32_t dbase =
                    sb + GSM_B + (buf * 2 + hl) * GB_BUF + kk * (GB_LD * 2);
#pragma unroll
                for (int s2 = 0; s2 < 2; s2++) {
                    const int s = (tid & 7) * 2 + s2;
                    CP_ASYNC16(dbase + s * 16, gsrc + s * 8);
                }
            }
        }
        CP_COMMIT();
    };

    load_chunk(0, 0);

    for (int c = 0; c < nChunks; c++) {
        if (c + 1 < nChunks) { load_chunk(c + 1, (c + 1) & 1); CP_WAIT(1); }
        else                 { CP_WAIT(0); }
        __syncthreads();

        const int buf = c & 1;
        const uint32_t abase_h = sb + GSM_A + (buf * 2 + 0) * GA_BUF;
        const uint32_t abase_l = sb + GSM_A + (buf * 2 + 1) * GA_BUF;
        const uint32_t bbase_h = sb + GSM_B + (buf * 2 + 0) * GB_BUF;
        const uint32_t bbase_l = sb + GSM_B + (buf * 2 + 1) * GB_BUF;

#pragma unroll
        for (int ks = 0; ks < 2; ks++) {
            uint32_t ah[2][4], al[2][4];
            const int arow = lane & 15;
            const int acol = ks * 16 + (lane >> 4) * 8;
#pragma unroll
            for (int mt = 0; mt < 2; mt++) {
                const uint32_t aoff =
                    ((wm * 32 + mt * 16 + arow) * GA_LD + acol) * 2;
                ldsm_x4(ah[mt], abase_h + aoff);
                ldsm_x4(al[mt], abase_l + aoff);
            }
            const int brow = ks * 16 + (lane & 15);
#pragma unroll
            for (int np = 0; np < 4; np++) {
                const uint32_t boff =
                    (brow * GB_LD + wn * 64 + np * 16 + (lane >> 4) * 8) * 2;
                uint32_t bh[4], bl[4];
                ldsm_x4t(bh, bbase_h + boff);
                ldsm_x4t(bl, bbase_l + boff);
#pragma unroll
                for (int sub = 0; sub < 2; sub++) {
                    const int nt = np * 2 + sub;
#pragma unroll
                    for (int mt = 0; mt < 2; mt++) {
                        mma_bf16(acc[mt][nt], ah[mt], bh[2 * sub], bh[2 * sub + 1]);
                        mma_bf16(acc[mt][nt], ah[mt], bl[2 * sub], bl[2 * sub + 1]);
                        mma_bf16(acc[mt][nt], al[mt], bh[2 * sub], bh[2 * sub + 1]);
                    }
                }
            }
        }
        __syncthreads();
    }

#pragma unroll
    for (int mt = 0; mt < 2; mt++) {
        const int r0 = rowBase + wm * 32 + mt * 16 + (lane >> 2);
#pragma unroll
        for (int nt = 0; nt < 8; nt++) {
            const int cc = wn * 64 + nt * 8 + (lane & 3) * 2;
            const float b0 = bias[cc], b1 = bias[cc + 1];
            float2 lo, hi;
            lo.x = fmaxf(acc[mt][nt][0] + b0, 0.0f);
            lo.y = fmaxf(acc[mt][nt][1] + b1, 0.0f);
            hi.x = fmaxf(acc[mt][nt][2] + b0, 0.0f);
            hi.y = fmaxf(acc[mt][nt][3] + b1, 0.0f);
            *(float2*)&C[(size_t)r0 * 128 + cc]       = lo;
            *(float2*)&C[(size_t)(r0 + 8) * 128 + cc] = hi;
        }
    }
}

// QKV grid-fused: grid(3, M/128). The three CTAs sharing blockIdx.y are
// adjacent in issue order -> co-resident -> A tile read from DRAM once,
// served from L2 twice. Also 1152 CTAs = ~3.9 waves (vs 3 x 1.3-wave tails).
__global__ __launch_bounds__(256, 2)
void qkv_grid_kernel(const __nv_bfloat16* __restrict__ Ahi,
                     const __nv_bfloat16* __restrict__ Alo,
                     const __nv_bfloat16* __restrict__ whi,
                     const __nv_bfloat16* __restrict__ wlo,
                     const float* __restrict__ bq,
                     const float* __restrict__ bk,
                     const float* __restrict__ bv,
                     float* __restrict__ qo, float* __restrict__ ko,
                     float* __restrict__ vo)
{
    extern __shared__ __align__(16) char smc[];
    const uint32_t sb = smem_to_u32(smc);
    const int wsel = blockIdx.x;
    const __nv_bfloat16* Whi = whi + (size_t)wsel * 49152;
    const __nv_bfloat16* Wlo = wlo + (size_t)wsel * 49152;
    const float* bias = (wsel == 0) ? bq : (wsel == 1) ? bk : bv;
    float* dst        = (wsel == 0) ? qo : (wsel == 1) ? ko : vo;
    gemm_core(Ahi, Alo, 384, 384, blockIdx.y * 128, Whi, Wlo, bias, dst, sb);
}

// Output projection (K = 128)
__global__ __launch_bounds__(256, 2)
void gemm_ps_kernel(const __nv_bfloat16* __restrict__ Ahi,
                    const __nv_bfloat16* __restrict__ Alo,
                    int lda, int K,
                    const __nv_bfloat16* __restrict__ Whi,
                    const __nv_bfloat16* __restrict__ Wlo,
                    const float* __restrict__ bias, float* __restrict__ C)
{
    extern __shared__ __align__(16) char smc[];
    const uint32_t sb = smem_to_u32(smc);
    gemm_core(Ahi, Alo, lda, K, blockIdx.x * 128, Whi, Wlo, bias, C, sb);
}

// ===========================================================================
// Attention v6 (round-13 winner, unchanged): S = 3-term bf16; log2-domain
// softmax (Q pre-scaled by 0.25*log2e, exp2f); PV = fp16 P x fp16 V single
// chain; O written pre-split bf16 hi/lo.
// ===========================================================================
#define KLD 520
#define VLD 24
#define KT_BYTES (16 * KLD * 2)
#define VS_BYTES (NSEQ * VLD * 2)
#define OFF_KT_HI 0
#define OFF_KT_LO (OFF_KT_HI + KT_BYTES)
#define OFF_VS    (OFF_KT_LO + KT_BYTES)
#define OFF_OBUF  (OFF_VS + VS_BYTES)
#define OFF_RED   (OFF_OBUF + 4 * 32 * 16 * 4)
#define ATTN_SMEM (OFF_RED + 4 * 32 * 8)          // 67072 bytes

#define QSCALE 0.3606737602f    /* 0.25 * log2(e) */

__global__ __launch_bounds__(256, 2)
void attn_tc_kernel(const float* __restrict__ q, const float* __restrict__ k,
                    const float* __restrict__ v,
                    __nv_bfloat16* __restrict__ ohi,
                    __nv_bfloat16* __restrict__ olo)
{
    extern __shared__ __align__(16) char smc[];
    const uint32_t sb = smem_to_u32(smc);
    __nv_bfloat16* kt_hi = (__nv_bfloat16*)(smc + OFF_KT_HI);
    __nv_bfloat16* kt_lo = (__nv_bfloat16*)(smc + OFF_KT_LO);
    __half*        vs    = (__half*)(smc + OFF_VS);
    float*  obuf   = (float*)(smc + OFF_OBUF);
    float2* redbuf = (float2*)(smc + OFF_RED);

    const int bt   = blockIdx.x;
    const int h    = blockIdx.y;
    const int tid  = threadIdx.x;
    const int warp = tid >> 5;
    const int lane = tid & 31;
    const int wm   = warp & 1;
    const int wn   = warp >> 1;
    const size_t base = (size_t)bt * NSEQ * DMODEL + h * DHEAD;

    for (int idx = tid; idx < NSEQ * 8; idx += 256) {
        const int m = idx >> 3, dp = (idx & 7) * 2;
        const float2 kv = *(const float2*)&k[base + (size_t)m * DMODEL + dp];
        uint32_t kh, kl;
        split2(kv.x, kv.y, kh, kl);
        kt_hi[dp * KLD + m] = __ushort_as_bfloat16((unsigned short)(kh & 0xffffu));
        kt_hi[(dp + 1) * KLD + m] = __ushort_as_bfloat16((unsigned short)(kh >> 16));
        kt_lo[dp * KLD + m] = __ushort_as_bfloat16((unsigned short)(kl & 0xffffu));
        kt_lo[(dp + 1) * KLD + m] = __ushort_as_bfloat16((unsigned short)(kl >> 16));

        const float2 vv = *(const float2*)&v[base + (size_t)m * DMODEL + dp];
        *(uint32_t*)&vs[m * VLD + dp] = packh2(vv.x, vv.y);
    }
    __syncthreads();

    const int lq = lane >> 2;
    const int lc = lane & 3;

    for (int t0 = 0; t0 < NSEQ; t0 += 32) {
        uint32_t qh[4], ql[4];
        {
            const float* qrow = q + base + (size_t)(t0 + wm * 16 + lq) * DMODEL;
            const float2 x0 = *(const float2*)&qrow[2 * lc];
            const float2 x1 = *(const float2*)&qrow[8 + 2 * lc];
            const float2 y0 = *(const float2*)&qrow[8 * DMODEL + 2 * lc];
            const float2 y1 = *(const float2*)&qrow[8 * DMODEL + 8 + 2 * lc];
            split2(QSCALE * x0.x, QSCALE * x0.y, qh[0], ql[0]);
            split2(QSCALE * y0.x, QSCALE * y0.y, qh[1], ql[1]);
            split2(QSCALE * x1.x, QSCALE * x1.y, qh[2], ql[2]);
            split2(QSCALE * y1.x, QSCALE * y1.y, qh[3], ql[3]);
        }

        float sacc[16][4];
#pragma unroll
        for (int nt = 0; nt < 16; nt++)
#pragma unroll
            for (int e = 0; e < 4; e++) sacc[nt][e] = 0.0f;

#pragma unroll
        for (int np = 0; np < 8; np++) {
            const int key0 = wn * 128 + np * 16;
            const uint32_t kaddr =
                sb + OFF_KT_HI + ((lane & 15) * KLD + key0 + (lane >> 4) * 8) * 2;
            uint32_t bh[4], bl[4];
            ldsm_x4t(bh, kaddr);
            ldsm_x4t(bl, kaddr + KT_BYTES);
#pragma unroll
            for (int sub = 0; sub < 2; sub++) {
                const int nt = np * 2 + sub;
                mma_bf16(sacc[nt], qh, bh[2 * sub], bh[2 * sub + 1]);
                mma_bf16(sacc[nt], qh, bl[2 * sub], bl[2 * sub + 1]);
                mma_bf16(sacc[nt], ql, bh[2 * sub], bh[2 * sub + 1]);
            }
        }

        float m0 = -1e30f, m1 = -1e30f;
#pragma unroll
        for (int nt = 0; nt < 16; nt++) {
            m0 = fmaxf(m0, fmaxf(sacc[nt][0], sacc[nt][1]));
            m1 = fmaxf(m1, fmaxf(sacc[nt][2], sacc[nt][3]));
        }
        m0 = fmaxf(m0, __shfl_xor_sync(0xffffffffu, m0, 1));
        m0 = fmaxf(m0, __shfl_xor_sync(0xffffffffu, m0, 2));
        m1 = fmaxf(m1, __shfl_xor_sync(0xffffffffu, m1, 1));
        m1 = fmaxf(m1, __shfl_xor_sync(0xffffffffu, m1, 2));

        float s0 = 0.0f, s1 = 0.0f;
#pragma unroll
        for (int nt = 0; nt < 16; nt++) {
            sacc[nt][0] = exp2f(sacc[nt][0] - m0); s0 += sacc[nt][0];
            sacc[nt][1] = exp2f(sacc[nt][1] - m0); s0 += sacc[nt][1];
            sacc[nt][2] = exp2f(sacc[nt][2] - m1); s1 += sacc[nt][2];
            sacc[nt][3] = exp2f(sacc[nt][3] - m1); s1 += sacc[nt][3];
        }
        s0 += __shfl_xor_sync(0xffffffffu, s0, 1);
        s0 += __shfl_xor_sync(0xffffffffu, s0, 2);
        s1 += __shfl_xor_sync(0xffffffffu, s1, 1);
        s1 += __shfl_xor_sync(0xffffffffu, s1, 2);

        if (lc == 0) {
            redbuf[wn * 32 + wm * 16 + lq]     = make_float2(m0, s0);
            redbuf[wn * 32 + wm * 16 + lq + 8] = make_float2(m1, s1);
        }
        __syncthreads();

        float scale0, scale1;
        {
            float M0 = -1e30f, M1 = -1e30f;
#pragma unroll
            for (int w = 0; w < 4; w++) {
                M0 = fmaxf(M0, redbuf[w * 32 + wm * 16 + lq].x);
                M1 = fmaxf(M1, redbuf[w * 32 + wm * 16 + lq + 8].x);
            }
            float t0v = 0.0f, t1v = 0.0f;
#pragma unroll
            for (int w = 0; w < 4; w++) {
                const float2 p0 = redbuf[w * 32 + wm * 16 + lq];
                const float2 p1 = redbuf[w * 32 + wm * 16 + lq + 8];
                t0v += exp2f(p0.x - M0) * p0.y;
                t1v += exp2f(p1.x - M1) * p1.y;
            }
            scale0 = exp2f(m0 - M0) / t0v;
            scale1 = exp2f(m1 - M1) / t1v;
        }

        float oac[2][4];
#pragma unroll
        for (int sub = 0; sub < 2; sub++)
#pragma unroll
            for (int e = 0; e < 4; e++) oac[sub][e] = 0.0f;

#pragma unroll
        for (int t = 0; t < 8; t++) {
            uint32_t ph[4];
            ph[0] = packh2(sacc[2*t][0]   * scale0, sacc[2*t][1]   * scale0);
            ph[1] = packh2(sacc[2*t][2]   * scale1, sacc[2*t][3]   * scale1);
            ph[2] = packh2(sacc[2*t+1][0] * scale0, sacc[2*t+1][1] * scale0);
            ph[3] = packh2(sacc[2*t+1][2] * scale1, sacc[2*t+1][3] * scale1);

            const int key0 = wn * 128 + t * 16;
            const uint32_t vaddr =
                sb + OFF_VS + ((key0 + (lane & 15)) * VLD + (lane >> 4) * 8) * 2;
            uint32_t vh[4];
            ldsm_x4t(vh, vaddr);
#pragma unroll
            for (int sub = 0; sub < 2; sub++)
                mma_f16(oac[sub], ph, vh[2 * sub], vh[2 * sub + 1]);
        }

        {
            float* ob = obuf + wn * 512;
            const int r0 = wm * 16 + lq;
#pragma unroll
            for (int sub = 0; sub < 2; sub++) {
                const int d0 = sub * 8 + 2 * lc;
                *(float2*)&ob[r0 * 16 + d0] =
                    make_float2(oac[sub][0], oac[sub][1]);
                *(float2*)&ob[(r0 + 8) * 16 + d0] =
                    make_float2(oac[sub][2], oac[sub][3]);
            }
        }
        __syncthreads();
        if (tid < 128) {
            const int q4  = tid * 4;
            const int row = q4 >> 4;
            const int d0  = q4 & 15;
            const float4 a = *(const float4*)&obuf[row * 16 + d0];
            const float4 b = *(const float4*)&obuf[512 + row * 16 + d0];
            const float4 c = *(const float4*)&obuf[1024 + row * 16 + d0];
            const float4 d = *(const float4*)&obuf[1536 + row * 16 + d0];
            float4 r;
            r.x = a.x + b.x + c.x + d.x;
            r.y = a.y + b.y + c.y + d.y;
            r.z = a.z + b.z + c.z + d.z;
            r.w = a.w + b.w + c.w + d.w;
            uint32_t h0, l0, h1, l1;
            split2(r.x, r.y, h0, l0);
            split2(r.z, r.w, h1, l1);
            const size_t go = base + (size_t)(t0 + row) * DMODEL + d0;
            *(uint2*)&ohi[go] = make_uint2(h0, h1);
            *(uint2*)&olo[go] = make_uint2(l0, l1);
        }
        __syncthreads();
    }
}

// ===========================================================================
extern "C" void kernel_launch(void* const* d_in, const int* in_sizes, int n_in,
                              void* d_out, int out_size)
{
    const float* X   = (const float*)d_in[0];
    const float* STE = (const float*)d_in[1];
    const float* Wq  = (const float*)d_in[2];
    const float* bq  = (const float*)d_in[3];
    const float* Wk  = (const float*)d_in[4];
    const float* bk  = (const float*)d_in[5];
    const float* Wv  = (const float*)d_in[6];
    const float* bv  = (const float*)d_in[7];
    const float* Wo  = (const float*)d_in[8];
    const float* bo  = (const float*)d_in[9];
    float* out = (float*)d_out;

    const int M  = in_sizes[0] / DMODEL;   // 49152
    const int BT = M / NSEQ;               // 96

    float *q, *k, *v;
    __nv_bfloat16 *ahi, *alo, *whi, *wlo, *ohi, *olo;
    cudaGetSymbolAddress((void**)&q,   g_q);
    cudaGetSymbolAddress((void**)&k,   g_k);
    cudaGetSymbolAddress((void**)&v,   g_v);
    cudaGetSymbolAddress((void**)&ahi, g_ahi);
    cudaGetSymbolAddress((void**)&alo, g_alo);
    cudaGetSymbolAddress((void**)&whi, g_whi);
    cudaGetSymbolAddress((void**)&wlo, g_wlo);
    cudaGetSymbolAddress((void**)&ohi, g_ohi);
    cudaGetSymbolAddress((void**)&olo, g_olo);

    presplit_x_kernel<<<4608, 256>>>(X, STE, M, ahi, alo);
    presplit_w_kernel<<<160, 256>>>(Wq, Wk, Wv, Wo, whi, wlo);

    cudaFuncSetAttribute(qkv_grid_kernel, cudaFuncAttributeMaxDynamicSharedMemorySize,
                         GEMM_SMEM);
    qkv_grid_kernel<<<dim3(3, M / 128), 256, GEMM_SMEM>>>(
        ahi, alo, whi, wlo, bq, bk, bv, q, k, v);

    cudaFuncSetAttribute(attn_tc_kernel, cudaFuncAttributeMaxDynamicSharedMemorySize,
                         ATTN_SMEM);
    attn_tc_kernel<<<dim3(BT, KHEADS), 256, ATTN_SMEM>>>(q, k, v, ohi, olo);

    cudaFuncSetAttribute(gemm_ps_kernel, cudaFuncAttributeMaxDynamicSharedMemorySize,
                         GEMM_SMEM);
    gemm_ps_kernel<<<M / 128, 256, GEMM_SMEM>>>(ohi, olo, 128, 128,
                                                whi + WOFF_O, wlo + WOFF_O, bo, out);
}